// round 16
// baseline (speedup 1.0000x reference)
#include <cuda_runtime.h>
#include <cuda_fp16.h>
#include <cstdint>
#include <math.h>

#define HW    12544   // 112*112
#define NTOK  12544   // 256 windows * 49 tokens

// ---------------- scratch (device globals; no allocation allowed) ----------
// __align__(256) is load-bearing: cp.async.cg 16B needs 16B-aligned global srcs.
__device__ __align__(256) __half g_xw [NTOK * 512];
__device__ __align__(256) __half g_qkv[NTOK * 1536];
__device__ __align__(256) __half g_att[NTOK * 512];
__device__ __align__(256) float  g_x1 [HW   * 512];
__device__ __align__(256) __half g_x2 [HW   * 512];
__device__ __align__(256) __half g_h  [NTOK * 2048];
__device__ __align__(256) __half g_wq[1536 * 512];
__device__ __align__(256) __half g_wp[512 * 512];
__device__ __align__(256) __half g_w1[2048 * 512];
__device__ __align__(256) __half g_w2[512 * 2048];
__device__ __align__(256) float  g_tbl[4 * 16 * 49 * 64];   // bias+mask table

// ---------------- helpers ----------------------------------------------------
__device__ __forceinline__ uint32_t smem_u32(const void* p) {
    uint32_t a;
    asm("{ .reg .u64 t; cvta.to.shared.u64 t, %1; cvt.u32.u64 %0, t; }" : "=r"(a) : "l"(p));
    return a;
}
__device__ __forceinline__ void cp16(uint32_t dst, const void* src) {
    asm volatile("cp.async.cg.shared.global [%0], [%1], 16;" :: "r"(dst), "l"(src));
}
__device__ __forceinline__ void ldmx4(uint32_t* r, uint32_t addr) {
    asm volatile("ldmatrix.sync.aligned.m8n8.x4.shared.b16 {%0,%1,%2,%3}, [%4];"
                 : "=r"(r[0]), "=r"(r[1]), "=r"(r[2]), "=r"(r[3]) : "r"(addr));
}
__device__ __forceinline__ void mma16(float* c, const uint32_t* a, uint32_t b0, uint32_t b1) {
    asm volatile(
        "mma.sync.aligned.m16n8k16.row.col.f32.f16.f16.f32 "
        "{%0,%1,%2,%3}, {%4,%5,%6,%7}, {%8,%9}, {%0,%1,%2,%3};"
        : "+f"(c[0]), "+f"(c[1]), "+f"(c[2]), "+f"(c[3])
        : "r"(a[0]), "r"(a[1]), "r"(a[2]), "r"(a[3]), "r"(b0), "r"(b1));
}
__device__ __forceinline__ int tok2pix(int t) {
    int win = t / 49, n = t % 49;
    int hs = (win >> 4) * 7 + n / 7;
    int ws = (win & 15) * 7 + n % 7;
    int ho = hs + 3; if (ho >= 112) ho -= 112;
    int wo = ws + 3; if (wo >= 112) wo -= 112;
    return ho * 112 + wo;
}
__device__ __forceinline__ int pix2tok(int p) {
    int ho = p / 112, wo = p % 112;
    int hs = ho - 3; if (hs < 0) hs += 112;
    int ws = wo - 3; if (ws < 0) ws += 112;
    return ((hs / 7) * 16 + ws / 7) * 49 + (hs % 7) * 7 + ws % 7;
}
__device__ __forceinline__ float gelu_tanh(float x) {
    float x3 = x * x * x;
    return 0.5f * x * (1.0f + tanhf(0.7978845608028654f * (x + 0.044715f * x3)));
}
__device__ __forceinline__ int region9(int h, int wv) {
    return ((h < 105) ? 0 : (h < 109 ? 1 : 2)) * 3 + ((wv < 105) ? 0 : (wv < 109 ? 1 : 2));
}
__device__ __forceinline__ void block_reduce2(float& s, float& q) {
    __shared__ float sh_s[8], sh_q[8];
    #pragma unroll
    for (int o = 16; o > 0; o >>= 1) {
        s += __shfl_down_sync(0xffffffffu, s, o);
        q += __shfl_down_sync(0xffffffffu, q, o);
    }
    int lane = threadIdx.x & 31, wid = threadIdx.x >> 5;
    if (lane == 0) { sh_s[wid] = s; sh_q[wid] = q; }
    __syncthreads();
    if (wid == 0) {
        s = (lane < 8) ? sh_s[lane] : 0.f;
        q = (lane < 8) ? sh_q[lane] : 0.f;
        #pragma unroll
        for (int o = 4; o > 0; o >>= 1) {
            s += __shfl_down_sync(0xffffffffu, s, o);
            q += __shfl_down_sync(0xffffffffu, q, o);
        }
        if (lane == 0) { sh_s[0] = s; sh_q[0] = q; }
    }
    __syncthreads();
    s = sh_s[0]; q = sh_q[0];
}

// ---------------- fused weight fp32 -> fp16 pre-pass (one launch) ------------
__global__ __launch_bounds__(256) void f2h_all(
    const float* __restrict__ s0, const float* __restrict__ s1,
    const float* __restrict__ s2, const float* __restrict__ s3,
    __half* __restrict__ d0, __half* __restrict__ d1,
    __half* __restrict__ d2, __half* __restrict__ d3)
{
    int i = blockIdx.x * 256 + threadIdx.x;
    int stride = gridDim.x * 256;
    for (; i < 786432; i += stride) {
        int j = i; const float* s; __half* d;
        if      (j < 196608) { s = s0; d = d0; }
        else if (j < 262144) { s = s1; d = d1; j -= 196608; }
        else if (j < 524288) { s = s2; d = d2; j -= 262144; }
        else                 { s = s3; d = d3; j -= 524288; }
        float4 v = ((const float4*)s)[j];
        ((__half2*)d)[j * 2]     = __floats2half2_rn(v.x, v.y);
        ((__half2*)d)[j * 2 + 1] = __floats2half2_rn(v.z, v.w);
    }
}

// ---------------- bias+mask table: tbl[cls][head][i][j64] --------------------
// cls = (wh==15)*2 + (ww==15). j in [49,64) and masked pairs get -1e9.
__global__ __launch_bounds__(256) void build_tbl(
    const float* __restrict__ rpb, float* __restrict__ tbl)
{
    int e = blockIdx.x * 256 + threadIdx.x;
    if (e >= 4 * 16 * 49 * 64) return;
    int j    = e & 63;
    int i    = (e >> 6) % 49;
    int head = (e / (49 * 64)) & 15;
    int cls  = e / (16 * 49 * 64);
    float val;
    if (j < 49) {
        int wh = (cls & 2) ? 15 : 0;
        int ww = (cls & 1) ? 15 : 0;
        int ri = i / 7, ci = i % 7, rj = j / 7, cj = j % 7;
        int regi = region9(wh * 7 + ri, ww * 7 + ci);
        int regj = region9(wh * 7 + rj, ww * 7 + cj);
        val = rpb[((ri - rj + 6) * 13 + (ci - cj + 6)) * 16 + head]
            + (regi == regj ? 0.f : -1e9f);
    } else val = -1e9f;
    tbl[e] = val;
}

// ---------------- LN1: coalesced, 32 pixels per block ------------------------
__global__ __launch_bounds__(256) void ln1_kernel(
    const float* __restrict__ x, const float* __restrict__ w,
    const float* __restrict__ b, __half* __restrict__ out)
{
    __shared__ float ssum[8][33], ssq[8][33];
    __shared__ float smean[32], srstd[32];
    __shared__ __half sbuf[32][514];
    int tid = threadIdx.x, px = tid & 31, cg = tid >> 5;
    int p = blockIdx.x * 32 + px;

    float s = 0.f, q = 0.f;
    #pragma unroll 8
    for (int ci = 0; ci < 64; ci++) {
        float v = x[(size_t)(cg * 64 + ci) * HW + p];
        s += v; q += v * v;
    }
    ssum[cg][px] = s; ssq[cg][px] = q;
    __syncthreads();
    if (tid < 32) {
        float S_ = 0.f, Q_ = 0.f;
        #pragma unroll
        for (int g2 = 0; g2 < 8; g2++) { S_ += ssum[g2][tid]; Q_ += ssq[g2][tid]; }
        float mean = S_ * (1.0f / 512.0f);
        float var  = Q_ * (1.0f / 512.0f) - mean * mean;
        smean[tid] = mean; srstd[tid] = rsqrtf(var + 1e-5f);
    }
    __syncthreads();
    float mean = smean[px], rstd = srstd[px];
    #pragma unroll 8
    for (int ci = 0; ci < 64; ci++) {
        int c = cg * 64 + ci;
        float v = x[(size_t)c * HW + p];
        sbuf[px][c] = __float2half_rn((v - mean) * rstd * __ldg(w + c) + __ldg(b + c));
    }
    __syncthreads();
    int p0 = blockIdx.x * 32;
    for (int r = 0; r < 32; r++) {
        int t = pix2tok(p0 + r);
        *(__half2*)(out + (size_t)t * 512 + tid * 2) = *(__half2*)&sbuf[r][tid * 2];
    }
}

// ---------------- LN2 ---------------------------------------------------------
__global__ __launch_bounds__(256) void ln2_kernel(
    const float* __restrict__ x, const float* __restrict__ w,
    const float* __restrict__ b, __half* __restrict__ out)
{
    int p = blockIdx.x;
    int c = threadIdx.x;
    float v1 = x[(size_t)p * 512 + c];
    float v2 = x[(size_t)p * 512 + c + 256];
    float s = v1 + v2, q = v1 * v1 + v2 * v2;
    block_reduce2(s, q);
    float mean = s * (1.0f / 512.0f);
    float var  = q * (1.0f / 512.0f) - mean * mean;
    float rstd = rsqrtf(var + 1e-5f);
    out[(size_t)p * 512 + c]       = __float2half_rn((v1 - mean) * rstd * w[c]       + b[c]);
    out[(size_t)p * 512 + c + 256] = __float2half_rn((v2 - mean) * rstd * w[c + 256] + b[c + 256]);
}

// ---------------- tensor-core windowed attention ------------------------------
__global__ __launch_bounds__(128) void attn_kernel(
    const __half* __restrict__ qkv, const float* __restrict__ tbl,
    __half* __restrict__ out)
{
    int w    = blockIdx.x >> 4;
    int head = blockIdx.x & 15;
    __shared__ __align__(16) __half Qh[64][40];
    __shared__ __align__(16) __half Kh[64][40];
    __shared__ __align__(16) __half Vt[32][72];
    __shared__ __align__(16) __half Ph[64][72];
    int tid = threadIdx.x, lane = tid & 31, wid = tid >> 5;

    __half2 z2 = __floats2half2_rn(0.f, 0.f);
    for (int idx = tid; idx < 15 * 16; idx += 128) {
        int r = 49 + idx / 16, c = (idx % 16) * 2;
        *(__half2*)&Qh[r][c] = z2;
        *(__half2*)&Kh[r][c] = z2;
    }
    for (int idx = tid; idx < 32 * 15; idx += 128) {
        int r = idx / 15, c = 49 + idx % 15;
        Vt[r][c] = __float2half(0.f);
    }
    for (int idx = tid; idx < 49 * 16; idx += 128) {
        int n = idx >> 4, dp = (idx & 15) * 2;
        const __half* base = qkv + (size_t)(w * 49 + n) * 1536 + head * 32 + dp;
        *(__half2*)&Qh[n][dp] = *(const __half2*)(base);
        *(__half2*)&Kh[n][dp] = *(const __half2*)(base + 512);
        __half2 v2 = *(const __half2*)(base + 1024);
        Vt[dp][n]     = __low2half(v2);
        Vt[dp + 1][n] = __high2half(v2);
    }
    __syncthreads();

    uint32_t sbQ = smem_u32(&Qh[0][0]);
    uint32_t sbK = smem_u32(&Kh[0][0]);
    uint32_t sbV = smem_u32(&Vt[0][0]);
    uint32_t sbP = smem_u32(&Ph[0][0]);

    float c[8][4];
    #pragma unroll
    for (int i = 0; i < 8; i++)
        #pragma unroll
        for (int r = 0; r < 4; r++) c[i][r] = 0.f;

    uint32_t aoff = sbQ + (uint32_t)(wid * 16 + (lane & 15)) * 80 + ((lane >> 4) ? 16u : 0u);
    uint32_t boff = sbK + (uint32_t)lane * 80;
    #pragma unroll
    for (int kk = 0; kk < 2; kk++) {
        uint32_t af[4], b0[4], b1[4], b2[4], b3[4];
        ldmx4(af, aoff + kk * 32);
        ldmx4(b0, boff + kk * 32);
        ldmx4(b1, boff + kk * 32 + 16);
        ldmx4(b2, boff + 32 * 80 + kk * 32);
        ldmx4(b3, boff + 32 * 80 + kk * 32 + 16);
        #pragma unroll
        for (int nt = 0; nt < 4; nt++) mma16(c[nt],     af, b0[nt], b1[nt]);
        #pragma unroll
        for (int nt = 0; nt < 4; nt++) mma16(c[4 + nt], af, b2[nt], b3[nt]);
    }

    int wh = w >> 4, ww = w & 15;
    int cls = ((wh == 15) ? 2 : 0) | ((ww == 15) ? 1 : 0);
    const float* tb = tbl + (size_t)(cls * 16 + head) * 49 * 64;
    int g = lane >> 2, t4 = lane & 3;
    #pragma unroll
    for (int r = 0; r < 2; r++) {
        int i = wid * 16 + g + r * 8;
        int il = (i < 49) ? i : 48;
        const float* trow = tb + il * 64 + t4 * 2;
        float m = -3.0e38f;
        #pragma unroll
        for (int nt = 0; nt < 8; nt++) {
            float2 tv = *(const float2*)(trow + nt * 8);
            float s0 = fmaf(c[nt][r * 2 + 0], 0.17677669529663687f, tv.x);
            float s1 = fmaf(c[nt][r * 2 + 1], 0.17677669529663687f, tv.y);
            c[nt][r * 2 + 0] = s0;
            c[nt][r * 2 + 1] = s1;
            m = fmaxf(m, fmaxf(s0, s1));
        }
        m = fmaxf(m, __shfl_xor_sync(0xffffffffu, m, 1));
        m = fmaxf(m, __shfl_xor_sync(0xffffffffu, m, 2));
        float sum = 0.f;
        #pragma unroll
        for (int nt = 0; nt < 8; nt++)
            #pragma unroll
            for (int e = 0; e < 2; e++) {
                float ev = __expf(c[nt][r * 2 + e] - m);
                c[nt][r * 2 + e] = ev;
                sum += ev;
            }
        sum += __shfl_xor_sync(0xffffffffu, sum, 1);
        sum += __shfl_xor_sync(0xffffffffu, sum, 2);
        float inv = 1.0f / sum;
        #pragma unroll
        for (int nt = 0; nt < 8; nt++) {
            __half2 h2 = __floats2half2_rn(c[nt][r * 2] * inv, c[nt][r * 2 + 1] * inv);
            *(__half2*)&Ph[i][nt * 8 + t4 * 2] = h2;
        }
    }
    __syncwarp();

    float o[4][4];
    #pragma unroll
    for (int i = 0; i < 4; i++)
        #pragma unroll
        for (int r = 0; r < 4; r++) o[i][r] = 0.f;

    uint32_t aoff2 = sbP + (uint32_t)(wid * 16 + (lane & 15)) * 144 + ((lane >> 4) ? 16u : 0u);
    uint32_t boff2 = sbV + (uint32_t)lane * 144;
    #pragma unroll
    for (int kk = 0; kk < 4; kk++) {
        uint32_t af[4], b0[4], b1[4];
        ldmx4(af, aoff2 + kk * 32);
        ldmx4(b0, boff2 + kk * 32);
        ldmx4(b1, boff2 + kk * 32 + 16);
        #pragma unroll
        for (int nt = 0; nt < 4; nt++) mma16(o[nt], af, b0[nt], b1[nt]);
    }

    #pragma unroll
    for (int r = 0; r < 2; r++) {
        int i = wid * 16 + g + r * 8;
        if (i < 49) {
            #pragma unroll
            for (int nt = 0; nt < 4; nt++) {
                int d = nt * 8 + t4 * 2;
                __half2 h2 = __floats2half2_rn(o[nt][r * 2], o[nt][r * 2 + 1]);
                *(__half2*)(out + (size_t)(w * 49 + i) * 512 + head * 32 + d) = h2;
            }
        }
    }
}

// ---------------- fp16 mma.sync GEMM: 256x128 tile, 512 thr, 3 stages --------
#define BM 256
#define BN 128
#define BKH 64
#define ROWB 144
#define A_BYTES (BM * ROWB)                    // 36864
#define B_BYTES (BN * ROWB)                    // 18432
#define STAGE_BYTES (A_BYTES + B_BYTES)        // 55296
#define NSTAGE 3
#define SM_BYTES (NSTAGE * STAGE_BYTES)        // 165888

__device__ __forceinline__ void load_chunk(
    const __half* __restrict__ A, const __half* __restrict__ B, int K,
    int m0, int n0, int tid, uint32_t stage_base, int ch)
{
    int kb = ch * BKH;
    uint32_t a_s = stage_base;
    uint32_t b_s = stage_base + A_BYTES;
    #pragma unroll
    for (int t = 0; t < 6; t++) {
        int idx = tid + t * 512;              // 0..3071
        if (idx < 2048) {
            int r = idx >> 3, c8 = idx & 7;
            cp16(a_s + (uint32_t)(r * ROWB + c8 * 16), A + (size_t)(m0 + r) * K + kb + c8 * 8);
        } else {
            int li = idx - 2048;
            int r = li >> 3, c8 = li & 7;
            cp16(b_s + (uint32_t)(r * ROWB + c8 * 16), B + (size_t)(n0 + r) * K + kb + c8 * 8);
        }
    }
    asm volatile("cp.async.commit_group;" ::: "memory");
}

template<int N, int K, int MODE>
__global__ __launch_bounds__(512, 1) void gemm_mma(
    const __half* __restrict__ A, const __half* __restrict__ B,
    const float* __restrict__ bias, const float* __restrict__ res,
    void* __restrict__ Cv)
{
    extern __shared__ __half sm[];
    uint32_t sb = smem_u32(sm);
    int tid = threadIdx.x;
    int wid = tid >> 5, lane = tid & 31;
    int g = lane >> 2, t4 = lane & 3;
    int wm = wid >> 2, wn = wid & 3;            // 4x4 warp grid, 64x32 warp tiles
    int m0 = blockIdx.y * BM, n0 = blockIdx.x * BN;

    uint32_t a_off = (uint32_t)(wm * 64 + (lane & 15)) * ROWB + ((lane >> 4) ? 16u : 0u);
    uint32_t b_off = (uint32_t)A_BYTES + (uint32_t)(wn * 32 + lane) * ROWB;

    float c[4][4][4];
    #pragma unroll
    for (int i = 0; i < 4; i++)
        #pragma unroll
        for (int j = 0; j < 4; j++)
            #pragma unroll
            for (int r = 0; r < 4; r++) c[i][j][r] = 0.f;

    constexpr int nch = K / BKH;
    load_chunk(A, B, K, m0, n0, tid, sb, 0);
    load_chunk(A, B, K, m0, n0, tid, sb + STAGE_BYTES, 1);

    int sidx = 0;
    #pragma unroll 1
    for (int ch = 0; ch < nch; ch++) {
        if (ch + 1 < nch) asm volatile("cp.async.wait_group 1;" ::: "memory");
        else              asm volatile("cp.async.wait_group 0;" ::: "memory");
        __syncthreads();

        if (ch + 2 < nch) {
            int ps = sidx + 2; if (ps >= NSTAGE) ps -= NSTAGE;
            load_chunk(A, B, K, m0, n0, tid, sb + ps * STAGE_BYTES, ch + 2);
        }

        uint32_t base = sb + sidx * STAGE_BYTES;
        uint32_t a_base = base + a_off;
        uint32_t b_base = base + b_off;
        #pragma unroll
        for (int ks = 0; ks < 4; ks++) {
            uint32_t kbyte = ks * 32;
            uint32_t af[4][4], bq0[4], bq1[4];
            #pragma unroll
            for (int mt = 0; mt < 4; mt++)
                ldmx4(af[mt], a_base + mt * (16 * ROWB) + kbyte);
            ldmx4(bq0, b_base + kbyte);
            ldmx4(bq1, b_base + kbyte + 16);
            #pragma unroll
            for (int mt = 0; mt < 4; mt++)
                #pragma unroll
                for (int nt = 0; nt < 4; nt++)
                    mma16(c[mt][nt], af[mt], bq0[nt], bq1[nt]);
        }
        if (++sidx == NSTAGE) sidx = 0;
    }

    if (MODE == 0) {
        __half* C = (__half*)Cv;
        #pragma unroll
        for (int mt = 0; mt < 4; mt++)
            #pragma unroll
            for (int hf = 0; hf < 2; hf++) {
                int m = m0 + wm * 64 + mt * 16 + g + hf * 8;
                #pragma unroll
                for (int nt = 0; nt < 4; nt++) {
                    int n = n0 + wn * 32 + nt * 8 + t4 * 2;
                    float v0 = c[mt][nt][hf * 2 + 0] + bias[n];
                    float v1 = c[mt][nt][hf * 2 + 1] + bias[n + 1];
                    *(__half2*)(C + (size_t)m * N + n) = __floats2half2_rn(v0, v1);
                }
            }
    } else if (MODE == 1) {
        __half* C = (__half*)Cv;
        #pragma unroll
        for (int mt = 0; mt < 4; mt++)
            #pragma unroll
            for (int hf = 0; hf < 2; hf++) {
                int m = m0 + wm * 64 + mt * 16 + g + hf * 8;
                #pragma unroll
                for (int nt = 0; nt < 4; nt++) {
                    int n = n0 + wn * 32 + nt * 8 + t4 * 2;
                    float v0 = gelu_tanh(c[mt][nt][hf * 2 + 0] + bias[n]);
                    float v1 = gelu_tanh(c[mt][nt][hf * 2 + 1] + bias[n + 1]);
                    *(__half2*)(C + (size_t)m * N + n) = __floats2half2_rn(v0, v1);
                }
            }
    } else if (MODE == 2) {
        float* C = (float*)Cv;
        #pragma unroll
        for (int mt = 0; mt < 4; mt++)
            #pragma unroll
            for (int hf = 0; hf < 2; hf++) {
                int m = m0 + wm * 64 + mt * 16 + g + hf * 8;
                int p = tok2pix(m);
                #pragma unroll
                for (int nt = 0; nt < 4; nt++) {
                    int n = n0 + wn * 32 + nt * 8 + t4 * 2;
                    float2 v = make_float2(
                        c[mt][nt][hf * 2 + 0] + bias[n]     + res[(size_t)n * HW + p],
                        c[mt][nt][hf * 2 + 1] + bias[n + 1] + res[(size_t)(n + 1) * HW + p]);
                    *(float2*)(C + (size_t)p * 512 + n) = v;
                }
            }
    } else {  // MODE 3
        float* C = (float*)Cv;
        #pragma unroll
        for (int mt = 0; mt < 4; mt++)
            #pragma unroll
            for (int hf = 0; hf < 2; hf++) {
                int m = m0 + wm * 64 + mt * 16 + g + hf * 8;
                #pragma unroll
                for (int nt = 0; nt < 4; nt++) {
                    int n = n0 + wn * 32 + nt * 8 + t4 * 2;
                    float r0 = res[(size_t)m * 512 + n];
                    float r1 = res[(size_t)m * 512 + n + 1];
                    C[(size_t)n * HW + m]       = c[mt][nt][hf * 2 + 0] + bias[n]     + r0;
                    C[(size_t)(n + 1) * HW + m] = c[mt][nt][hf * 2 + 1] + bias[n + 1] + r1;
                }
            }
    }
}

// ---------------- launcher --------------------------------------------------
extern "C" void kernel_launch(void* const* d_in, const int* in_sizes, int n_in,
                              void* d_out, int out_size)
{
    const float* x     = (const float*)d_in[0];
    const float* n1w   = (const float*)d_in[1];
    const float* n1b   = (const float*)d_in[2];
    const float* qkvw  = (const float*)d_in[3];
    const float* qkvb  = (const float*)d_in[4];
    const float* projw = (const float*)d_in[5];
    const float* projb = (const float*)d_in[6];
    const float* rpb   = (const float*)d_in[7];
    const float* n2w   = (const float*)d_in[8];
    const float* n2b   = (const float*)d_in[9];
    const float* f1w   = (const float*)d_in[10];
    const float* f1b   = (const float*)d_in[11];
    const float* f2w   = (const float*)d_in[12];
    const float* f2b   = (const float*)d_in[13];
    float* out = (float*)d_out;

    __half *xw, *qkv, *att, *x2, *h, *wq, *wp, *w1, *w2;
    float *x1, *tbl;
    cudaGetSymbolAddress((void**)&xw,  g_xw);
    cudaGetSymbolAddress((void**)&qkv, g_qkv);
    cudaGetSymbolAddress((void**)&att, g_att);
    cudaGetSymbolAddress((void**)&x1,  g_x1);
    cudaGetSymbolAddress((void**)&x2,  g_x2);
    cudaGetSymbolAddress((void**)&h,   g_h);
    cudaGetSymbolAddress((void**)&wq,  g_wq);
    cudaGetSymbolAddress((void**)&wp,  g_wp);
    cudaGetSymbolAddress((void**)&w1,  g_w1);
    cudaGetSymbolAddress((void**)&w2,  g_w2);
    cudaGetSymbolAddress((void**)&tbl, g_tbl);

    cudaFuncSetAttribute(gemm_mma<1536, 512, 0>,  cudaFuncAttributeMaxDynamicSharedMemorySize, SM_BYTES);
    cudaFuncSetAttribute(gemm_mma<512, 512, 2>,   cudaFuncAttributeMaxDynamicSharedMemorySize, SM_BYTES);
    cudaFuncSetAttribute(gemm_mma<2048, 512, 1>,  cudaFuncAttributeMaxDynamicSharedMemorySize, SM_BYTES);
    cudaFuncSetAttribute(gemm_mma<512, 2048, 3>,  cudaFuncAttributeMaxDynamicSharedMemorySize, SM_BYTES);

    f2h_all<<<512, 256>>>(qkvw, projw, f1w, f2w, wq, wp, w1, w2);
    build_tbl<<<(4 * 16 * 49 * 64 + 255) / 256, 256>>>(rpb, tbl);
    ln1_kernel<<<HW / 32, 256>>>(x, n1w, n1b, xw);
    gemm_mma<1536, 512, 0><<<dim3(1536 / BN, NTOK / BM), 512, SM_BYTES>>>(xw, wq, qkvb, nullptr, qkv);
    attn_kernel<<<256 * 16, 128>>>(qkv, tbl, att);
    gemm_mma<512, 512, 2><<<dim3(512 / BN, NTOK / BM), 512, SM_BYTES>>>(att, wp, projb, x, x1);
    ln2_kernel<<<HW, 256>>>(x1, n2w, n2b, x2);
    gemm_mma<2048, 512, 1><<<dim3(2048 / BN, NTOK / BM), 512, SM_BYTES>>>(x2, w1, f1b, nullptr, h);
    gemm_mma<512, 2048, 3><<<dim3(512 / BN, NTOK / BM), 512, SM_BYTES>>>(h, w2, f2b, x1, out);
}

// round 17
// speedup vs baseline: 1.1349x; 1.1349x over previous
#include <cuda_runtime.h>
#include <cuda_fp16.h>
#include <cstdint>
#include <math.h>

#define HW    12544   // 112*112
#define NTOK  12544   // 256 windows * 49 tokens

// ---------------- scratch (device globals; no allocation allowed) ----------
// __align__(256) is load-bearing: cp.async.cg 16B needs 16B-aligned global srcs.
__device__ __align__(256) __half g_xw [NTOK * 512];
__device__ __align__(256) __half g_qkv[NTOK * 1536];
__device__ __align__(256) __half g_att[NTOK * 512];
__device__ __align__(256) float  g_x1 [HW   * 512];
__device__ __align__(256) __half g_x2 [HW   * 512];
__device__ __align__(256) __half g_h  [NTOK * 2048];
__device__ __align__(256) __half g_wq[1536 * 512];
__device__ __align__(256) __half g_wp[512 * 512];
__device__ __align__(256) __half g_w1[2048 * 512];
__device__ __align__(256) __half g_w2[512 * 2048];
__device__ __align__(256) float  g_tbl[4 * 16 * 49 * 64];   // bias+mask table

// ---------------- helpers ----------------------------------------------------
__device__ __forceinline__ uint32_t smem_u32(const void* p) {
    uint32_t a;
    asm("{ .reg .u64 t; cvta.to.shared.u64 t, %1; cvt.u32.u64 %0, t; }" : "=r"(a) : "l"(p));
    return a;
}
__device__ __forceinline__ void cp16(uint32_t dst, const void* src) {
    asm volatile("cp.async.cg.shared.global [%0], [%1], 16;" :: "r"(dst), "l"(src));
}
__device__ __forceinline__ void ldmx4(uint32_t* r, uint32_t addr) {
    asm volatile("ldmatrix.sync.aligned.m8n8.x4.shared.b16 {%0,%1,%2,%3}, [%4];"
                 : "=r"(r[0]), "=r"(r[1]), "=r"(r[2]), "=r"(r[3]) : "r"(addr));
}
__device__ __forceinline__ void mma16(float* c, const uint32_t* a, uint32_t b0, uint32_t b1) {
    asm volatile(
        "mma.sync.aligned.m16n8k16.row.col.f32.f16.f16.f32 "
        "{%0,%1,%2,%3}, {%4,%5,%6,%7}, {%8,%9}, {%0,%1,%2,%3};"
        : "+f"(c[0]), "+f"(c[1]), "+f"(c[2]), "+f"(c[3])
        : "r"(a[0]), "r"(a[1]), "r"(a[2]), "r"(a[3]), "r"(b0), "r"(b1));
}
__device__ __forceinline__ int tok2pix(int t) {
    int win = t / 49, n = t % 49;
    int hs = (win >> 4) * 7 + n / 7;
    int ws = (win & 15) * 7 + n % 7;
    int ho = hs + 3; if (ho >= 112) ho -= 112;
    int wo = ws + 3; if (wo >= 112) wo -= 112;
    return ho * 112 + wo;
}
__device__ __forceinline__ int pix2tok(int p) {
    int ho = p / 112, wo = p % 112;
    int hs = ho - 3; if (hs < 0) hs += 112;
    int ws = wo - 3; if (ws < 0) ws += 112;
    return ((hs / 7) * 16 + ws / 7) * 49 + (hs % 7) * 7 + ws % 7;
}
__device__ __forceinline__ float gelu_tanh(float x) {
    float x3 = x * x * x;
    return 0.5f * x * (1.0f + tanhf(0.7978845608028654f * (x + 0.044715f * x3)));
}
__device__ __forceinline__ int region9(int h, int wv) {
    return ((h < 105) ? 0 : (h < 109 ? 1 : 2)) * 3 + ((wv < 105) ? 0 : (wv < 109 ? 1 : 2));
}
__device__ __forceinline__ void block_reduce2(float& s, float& q) {
    __shared__ float sh_s[8], sh_q[8];
    #pragma unroll
    for (int o = 16; o > 0; o >>= 1) {
        s += __shfl_down_sync(0xffffffffu, s, o);
        q += __shfl_down_sync(0xffffffffu, q, o);
    }
    int lane = threadIdx.x & 31, wid = threadIdx.x >> 5;
    if (lane == 0) { sh_s[wid] = s; sh_q[wid] = q; }
    __syncthreads();
    if (wid == 0) {
        s = (lane < 8) ? sh_s[lane] : 0.f;
        q = (lane < 8) ? sh_q[lane] : 0.f;
        #pragma unroll
        for (int o = 4; o > 0; o >>= 1) {
            s += __shfl_down_sync(0xffffffffu, s, o);
            q += __shfl_down_sync(0xffffffffu, q, o);
        }
        if (lane == 0) { sh_s[0] = s; sh_q[0] = q; }
    }
    __syncthreads();
    s = sh_s[0]; q = sh_q[0];
}

// ---------------- fused weight fp32 -> fp16 pre-pass (one launch) ------------
__global__ __launch_bounds__(256) void f2h_all(
    const float* __restrict__ s0, const float* __restrict__ s1,
    const float* __restrict__ s2, const float* __restrict__ s3,
    __half* __restrict__ d0, __half* __restrict__ d1,
    __half* __restrict__ d2, __half* __restrict__ d3)
{
    int i = blockIdx.x * 256 + threadIdx.x;
    int stride = gridDim.x * 256;
    for (; i < 786432; i += stride) {
        int j = i; const float* s; __half* d;
        if      (j < 196608) { s = s0; d = d0; }
        else if (j < 262144) { s = s1; d = d1; j -= 196608; }
        else if (j < 524288) { s = s2; d = d2; j -= 262144; }
        else                 { s = s3; d = d3; j -= 524288; }
        float4 v = ((const float4*)s)[j];
        ((__half2*)d)[j * 2]     = __floats2half2_rn(v.x, v.y);
        ((__half2*)d)[j * 2 + 1] = __floats2half2_rn(v.z, v.w);
    }
}

// ---------------- bias+mask table: tbl[cls][head][i][j64] --------------------
__global__ __launch_bounds__(256) void build_tbl(
    const float* __restrict__ rpb, float* __restrict__ tbl)
{
    int e = blockIdx.x * 256 + threadIdx.x;
    if (e >= 4 * 16 * 49 * 64) return;
    int j    = e & 63;
    int i    = (e >> 6) % 49;
    int head = (e / (49 * 64)) & 15;
    int cls  = e / (16 * 49 * 64);
    float val;
    if (j < 49) {
        int wh = (cls & 2) ? 15 : 0;
        int ww = (cls & 1) ? 15 : 0;
        int ri = i / 7, ci = i % 7, rj = j / 7, cj = j % 7;
        int regi = region9(wh * 7 + ri, ww * 7 + ci);
        int regj = region9(wh * 7 + rj, ww * 7 + cj);
        val = rpb[((ri - rj + 6) * 13 + (ci - cj + 6)) * 16 + head]
            + (regi == regj ? 0.f : -1e9f);
    } else val = -1e9f;
    tbl[e] = val;
}

// ---------------- LN1: coalesced, 32 pixels per block ------------------------
__global__ __launch_bounds__(256) void ln1_kernel(
    const float* __restrict__ x, const float* __restrict__ w,
    const float* __restrict__ b, __half* __restrict__ out)
{
    __shared__ float ssum[8][33], ssq[8][33];
    __shared__ float smean[32], srstd[32];
    __shared__ __half sbuf[32][514];
    int tid = threadIdx.x, px = tid & 31, cg = tid >> 5;
    int p = blockIdx.x * 32 + px;

    float s = 0.f, q = 0.f;
    #pragma unroll 8
    for (int ci = 0; ci < 64; ci++) {
        float v = x[(size_t)(cg * 64 + ci) * HW + p];
        s += v; q += v * v;
    }
    ssum[cg][px] = s; ssq[cg][px] = q;
    __syncthreads();
    if (tid < 32) {
        float S_ = 0.f, Q_ = 0.f;
        #pragma unroll
        for (int g2 = 0; g2 < 8; g2++) { S_ += ssum[g2][tid]; Q_ += ssq[g2][tid]; }
        float mean = S_ * (1.0f / 512.0f);
        float var  = Q_ * (1.0f / 512.0f) - mean * mean;
        smean[tid] = mean; srstd[tid] = rsqrtf(var + 1e-5f);
    }
    __syncthreads();
    float mean = smean[px], rstd = srstd[px];
    #pragma unroll 8
    for (int ci = 0; ci < 64; ci++) {
        int c = cg * 64 + ci;
        float v = x[(size_t)c * HW + p];
        sbuf[px][c] = __float2half_rn((v - mean) * rstd * __ldg(w + c) + __ldg(b + c));
    }
    __syncthreads();
    int p0 = blockIdx.x * 32;
    for (int r = 0; r < 32; r++) {
        int t = pix2tok(p0 + r);
        *(__half2*)(out + (size_t)t * 512 + tid * 2) = *(__half2*)&sbuf[r][tid * 2];
    }
}

// ---------------- LN2 ---------------------------------------------------------
__global__ __launch_bounds__(256) void ln2_kernel(
    const float* __restrict__ x, const float* __restrict__ w,
    const float* __restrict__ b, __half* __restrict__ out)
{
    int p = blockIdx.x;
    int c = threadIdx.x;
    float v1 = x[(size_t)p * 512 + c];
    float v2 = x[(size_t)p * 512 + c + 256];
    float s = v1 + v2, q = v1 * v1 + v2 * v2;
    block_reduce2(s, q);
    float mean = s * (1.0f / 512.0f);
    float var  = q * (1.0f / 512.0f) - mean * mean;
    float rstd = rsqrtf(var + 1e-5f);
    out[(size_t)p * 512 + c]       = __float2half_rn((v1 - mean) * rstd * w[c]       + b[c]);
    out[(size_t)p * 512 + c + 256] = __float2half_rn((v2 - mean) * rstd * w[c + 256] + b[c + 256]);
}

// ---------------- tensor-core windowed attention (with table) ----------------
__global__ __launch_bounds__(128) void attn_kernel(
    const __half* __restrict__ qkv, const float* __restrict__ tbl,
    __half* __restrict__ out)
{
    int w    = blockIdx.x >> 4;
    int head = blockIdx.x & 15;
    __shared__ __align__(16) __half Qh[64][40];
    __shared__ __align__(16) __half Kh[64][40];
    __shared__ __align__(16) __half Vt[32][72];
    __shared__ __align__(16) __half Ph[64][72];
    int tid = threadIdx.x, lane = tid & 31, wid = tid >> 5;

    __half2 z2 = __floats2half2_rn(0.f, 0.f);
    for (int idx = tid; idx < 15 * 16; idx += 128) {
        int r = 49 + idx / 16, c = (idx % 16) * 2;
        *(__half2*)&Qh[r][c] = z2;
        *(__half2*)&Kh[r][c] = z2;
    }
    for (int idx = tid; idx < 32 * 15; idx += 128) {
        int r = idx / 15, c = 49 + idx % 15;
        Vt[r][c] = __float2half(0.f);
    }
    for (int idx = tid; idx < 49 * 16; idx += 128) {
        int n = idx >> 4, dp = (idx & 15) * 2;
        const __half* base = qkv + (size_t)(w * 49 + n) * 1536 + head * 32 + dp;
        *(__half2*)&Qh[n][dp] = *(const __half2*)(base);
        *(__half2*)&Kh[n][dp] = *(const __half2*)(base + 512);
        __half2 v2 = *(const __half2*)(base + 1024);
        Vt[dp][n]     = __low2half(v2);
        Vt[dp + 1][n] = __high2half(v2);
    }
    __syncthreads();

    uint32_t sbQ = smem_u32(&Qh[0][0]);
    uint32_t sbK = smem_u32(&Kh[0][0]);
    uint32_t sbV = smem_u32(&Vt[0][0]);
    uint32_t sbP = smem_u32(&Ph[0][0]);

    float c[8][4];
    #pragma unroll
    for (int i = 0; i < 8; i++)
        #pragma unroll
        for (int r = 0; r < 4; r++) c[i][r] = 0.f;

    uint32_t aoff = sbQ + (uint32_t)(wid * 16 + (lane & 15)) * 80 + ((lane >> 4) ? 16u : 0u);
    uint32_t boff = sbK + (uint32_t)lane * 80;
    #pragma unroll
    for (int kk = 0; kk < 2; kk++) {
        uint32_t af[4], b0[4], b1[4], b2[4], b3[4];
        ldmx4(af, aoff + kk * 32);
        ldmx4(b0, boff + kk * 32);
        ldmx4(b1, boff + kk * 32 + 16);
        ldmx4(b2, boff + 32 * 80 + kk * 32);
        ldmx4(b3, boff + 32 * 80 + kk * 32 + 16);
        #pragma unroll
        for (int nt = 0; nt < 4; nt++) mma16(c[nt],     af, b0[nt], b1[nt]);
        #pragma unroll
        for (int nt = 0; nt < 4; nt++) mma16(c[4 + nt], af, b2[nt], b3[nt]);
    }

    int wh = w >> 4, ww = w & 15;
    int cls = ((wh == 15) ? 2 : 0) | ((ww == 15) ? 1 : 0);
    const float* tb = tbl + (size_t)(cls * 16 + head) * 49 * 64;
    int g = lane >> 2, t4 = lane & 3;
    #pragma unroll
    for (int r = 0; r < 2; r++) {
        int i = wid * 16 + g + r * 8;
        int il = (i < 49) ? i : 48;
        const float* trow = tb + il * 64 + t4 * 2;
        float m = -3.0e38f;
        #pragma unroll
        for (int nt = 0; nt < 8; nt++) {
            float2 tv = *(const float2*)(trow + nt * 8);
            float s0 = fmaf(c[nt][r * 2 + 0], 0.17677669529663687f, tv.x);
            float s1 = fmaf(c[nt][r * 2 + 1], 0.17677669529663687f, tv.y);
            c[nt][r * 2 + 0] = s0;
            c[nt][r * 2 + 1] = s1;
            m = fmaxf(m, fmaxf(s0, s1));
        }
        m = fmaxf(m, __shfl_xor_sync(0xffffffffu, m, 1));
        m = fmaxf(m, __shfl_xor_sync(0xffffffffu, m, 2));
        float sum = 0.f;
        #pragma unroll
        for (int nt = 0; nt < 8; nt++)
            #pragma unroll
            for (int e = 0; e < 2; e++) {
                float ev = __expf(c[nt][r * 2 + e] - m);
                c[nt][r * 2 + e] = ev;
                sum += ev;
            }
        sum += __shfl_xor_sync(0xffffffffu, sum, 1);
        sum += __shfl_xor_sync(0xffffffffu, sum, 2);
        float inv = 1.0f / sum;
        #pragma unroll
        for (int nt = 0; nt < 8; nt++) {
            __half2 h2 = __floats2half2_rn(c[nt][r * 2] * inv, c[nt][r * 2 + 1] * inv);
            *(__half2*)&Ph[i][nt * 8 + t4 * 2] = h2;
        }
    }
    __syncwarp();

    float o[4][4];
    #pragma unroll
    for (int i = 0; i < 4; i++)
        #pragma unroll
        for (int r = 0; r < 4; r++) o[i][r] = 0.f;

    uint32_t aoff2 = sbP + (uint32_t)(wid * 16 + (lane & 15)) * 144 + ((lane >> 4) ? 16u : 0u);
    uint32_t boff2 = sbV + (uint32_t)lane * 144;
    #pragma unroll
    for (int kk = 0; kk < 4; kk++) {
        uint32_t af[4], b0[4], b1[4];
        ldmx4(af, aoff2 + kk * 32);
        ldmx4(b0, boff2 + kk * 32);
        ldmx4(b1, boff2 + kk * 32 + 16);
        #pragma unroll
        for (int nt = 0; nt < 4; nt++) mma16(o[nt], af, b0[nt], b1[nt]);
    }

    #pragma unroll
    for (int r = 0; r < 2; r++) {
        int i = wid * 16 + g + r * 8;
        if (i < 49) {
            #pragma unroll
            for (int nt = 0; nt < 4; nt++) {
                int d = nt * 8 + t4 * 2;
                __half2 h2 = __floats2half2_rn(o[nt][r * 2], o[nt][r * 2 + 1]);
                *(__half2*)(out + (size_t)(w * 49 + i) * 512 + head * 32 + d) = h2;
            }
        }
    }
}

// ---------------- fp16 mma.sync GEMM: 128x128 tile, 256 thr, 3 stages --------
// (reverted to the R15 config: 2 CTAs/SM, proven fastest)
#define BM 128
#define BN 128
#define BKH 64
#define PADH 72
#define ROWB 144
#define BUF_HALFS (BM * PADH)                 // 9216 halves
#define STAGE_BYTES (2 * BUF_HALFS * 2)       // 36864 B
#define NSTAGE 3
#define SM_BYTES (NSTAGE * STAGE_BYTES)       // 110592 B

__device__ __forceinline__ void load_chunk(
    const __half* __restrict__ A, const __half* __restrict__ B, int K,
    int m0, int n0, int tid, uint32_t stage_base, int ch)
{
    int kb = ch * BKH;
    uint32_t a_s = stage_base;
    uint32_t b_s = stage_base + BUF_HALFS * 2;
    #pragma unroll
    for (int t = 0; t < 8; t++) {
        int idx = tid + t * 256;
        int li  = idx & 1023;
        int r = li >> 3, c8 = li & 7;
        uint32_t so = (uint32_t)(r * ROWB + c8 * 16);
        if (idx < 1024)
            cp16(a_s + so, A + (size_t)(m0 + r) * K + kb + c8 * 8);
        else
            cp16(b_s + so, B + (size_t)(n0 + r) * K + kb + c8 * 8);
    }
    asm volatile("cp.async.commit_group;" ::: "memory");
}

template<int N, int K, int MODE>
__global__ __launch_bounds__(256, 2) void gemm_mma(
    const __half* __restrict__ A, const __half* __restrict__ B,
    const float* __restrict__ bias, const float* __restrict__ res,
    void* __restrict__ Cv)
{
    extern __shared__ __half sm[];
    uint32_t sb = smem_u32(sm);
    int tid = threadIdx.x;
    int wid = tid >> 5, lane = tid & 31;
    int g = lane >> 2, t4 = lane & 3;
    int wm = wid >> 2, wn = wid & 3;
    int m0 = blockIdx.y * BM, n0 = blockIdx.x * BN;

    uint32_t a_off = (uint32_t)(wm * 64 + (lane & 15)) * ROWB + ((lane >> 4) ? 16u : 0u);
    uint32_t b_off = (uint32_t)(wn * 32 + lane) * ROWB + (uint32_t)(BUF_HALFS * 2);

    float c[4][4][4];
    #pragma unroll
    for (int i = 0; i < 4; i++)
        #pragma unroll
        for (int j = 0; j < 4; j++)
            #pragma unroll
            for (int r = 0; r < 4; r++) c[i][j][r] = 0.f;

    constexpr int nch = K / BKH;
    load_chunk(A, B, K, m0, n0, tid, sb, 0);
    load_chunk(A, B, K, m0, n0, tid, sb + STAGE_BYTES, 1);

    int sidx = 0;
    #pragma unroll 1
    for (int ch = 0; ch < nch; ch++) {
        if (ch + 1 < nch) asm volatile("cp.async.wait_group 1;" ::: "memory");
        else              asm volatile("cp.async.wait_group 0;" ::: "memory");
        __syncthreads();

        if (ch + 2 < nch) {
            int ps = sidx + 2; if (ps >= NSTAGE) ps -= NSTAGE;
            load_chunk(A, B, K, m0, n0, tid, sb + ps * STAGE_BYTES, ch + 2);
        }

        uint32_t base = sb + sidx * STAGE_BYTES;
        uint32_t a_base = base + a_off;
        uint32_t b_base = base + b_off;
        #pragma unroll
        for (int ks = 0; ks < 4; ks++) {
            uint32_t kbyte = ks * 32;
            uint32_t af[4][4], bq0[4], bq1[4];
            #pragma unroll
            for (int mt = 0; mt < 4; mt++)
                ldmx4(af[mt], a_base + mt * (16 * ROWB) + kbyte);
            ldmx4(bq0, b_base + kbyte);
            ldmx4(bq1, b_base + kbyte + 16);
            #pragma unroll
            for (int mt = 0; mt < 4; mt++)
                #pragma unroll
                for (int nt = 0; nt < 4; nt++)
                    mma16(c[mt][nt], af[mt], bq0[nt], bq1[nt]);
        }
        if (++sidx == NSTAGE) sidx = 0;
    }

    if (MODE == 0) {
        __half* C = (__half*)Cv;
        #pragma unroll
        for (int mt = 0; mt < 4; mt++)
            #pragma unroll
            for (int hf = 0; hf < 2; hf++) {
                int m = m0 + wm * 64 + mt * 16 + g + hf * 8;
                #pragma unroll
                for (int nt = 0; nt < 4; nt++) {
                    int n = n0 + wn * 32 + nt * 8 + t4 * 2;
                    float v0 = c[mt][nt][hf * 2 + 0] + bias[n];
                    float v1 = c[mt][nt][hf * 2 + 1] + bias[n + 1];
                    *(__half2*)(C + (size_t)m * N + n) = __floats2half2_rn(v0, v1);
                }
            }
    } else if (MODE == 1) {
        __half* C = (__half*)Cv;
        #pragma unroll
        for (int mt = 0; mt < 4; mt++)
            #pragma unroll
            for (int hf = 0; hf < 2; hf++) {
                int m = m0 + wm * 64 + mt * 16 + g + hf * 8;
                #pragma unroll
                for (int nt = 0; nt < 4; nt++) {
                    int n = n0 + wn * 32 + nt * 8 + t4 * 2;
                    float v0 = gelu_tanh(c[mt][nt][hf * 2 + 0] + bias[n]);
                    float v1 = gelu_tanh(c[mt][nt][hf * 2 + 1] + bias[n + 1]);
                    *(__half2*)(C + (size_t)m * N + n) = __floats2half2_rn(v0, v1);
                }
            }
    } else if (MODE == 2) {
        float* C = (float*)Cv;
        #pragma unroll
        for (int mt = 0; mt < 4; mt++)
            #pragma unroll
            for (int hf = 0; hf < 2; hf++) {
                int m = m0 + wm * 64 + mt * 16 + g + hf * 8;
                int p = tok2pix(m);
                #pragma unroll
                for (int nt = 0; nt < 4; nt++) {
                    int n = n0 + wn * 32 + nt * 8 + t4 * 2;
                    float2 v = make_float2(
                        c[mt][nt][hf * 2 + 0] + bias[n]     + res[(size_t)n * HW + p],
                        c[mt][nt][hf * 2 + 1] + bias[n + 1] + res[(size_t)(n + 1) * HW + p]);
                    *(float2*)(C + (size_t)p * 512 + n) = v;
                }
            }
    } else {  // MODE 3
        float* C = (float*)Cv;
        #pragma unroll
        for (int mt = 0; mt < 4; mt++)
            #pragma unroll
            for (int hf = 0; hf < 2; hf++) {
                int m = m0 + wm * 64 + mt * 16 + g + hf * 8;
                #pragma unroll
                for (int nt = 0; nt < 4; nt++) {
                    int n = n0 + wn * 32 + nt * 8 + t4 * 2;
                    float r0 = res[(size_t)m * 512 + n];
                    float r1 = res[(size_t)m * 512 + n + 1];
                    C[(size_t)n * HW + m]       = c[mt][nt][hf * 2 + 0] + bias[n]     + r0;
                    C[(size_t)(n + 1) * HW + m] = c[mt][nt][hf * 2 + 1] + bias[n + 1] + r1;
                }
            }
    }
}

// ---------------- launcher --------------------------------------------------
extern "C" void kernel_launch(void* const* d_in, const int* in_sizes, int n_in,
                              void* d_out, int out_size)
{
    const float* x     = (const float*)d_in[0];
    const float* n1w   = (const float*)d_in[1];
    const float* n1b   = (const float*)d_in[2];
    const float* qkvw  = (const float*)d_in[3];
    const float* qkvb  = (const float*)d_in[4];
    const float* projw = (const float*)d_in[5];
    const float* projb = (const float*)d_in[6];
    const float* rpb   = (const float*)d_in[7];
    const float* n2w   = (const float*)d_in[8];
    const float* n2b   = (const float*)d_in[9];
    const float* f1w   = (const float*)d_in[10];
    const float* f1b   = (const float*)d_in[11];
    const float* f2w   = (const float*)d_in[12];
    const float* f2b   = (const float*)d_in[13];
    float* out = (float*)d_out;

    __half *xw, *qkv, *att, *x2, *h, *wq, *wp, *w1, *w2;
    float *x1, *tbl;
    cudaGetSymbolAddress((void**)&xw,  g_xw);
    cudaGetSymbolAddress((void**)&qkv, g_qkv);
    cudaGetSymbolAddress((void**)&att, g_att);
    cudaGetSymbolAddress((void**)&x1,  g_x1);
    cudaGetSymbolAddress((void**)&x2,  g_x2);
    cudaGetSymbolAddress((void**)&h,   g_h);
    cudaGetSymbolAddress((void**)&wq,  g_wq);
    cudaGetSymbolAddress((void**)&wp,  g_wp);
    cudaGetSymbolAddress((void**)&w1,  g_w1);
    cudaGetSymbolAddress((void**)&w2,  g_w2);
    cudaGetSymbolAddress((void**)&tbl, g_tbl);

    cudaFuncSetAttribute(gemm_mma<1536, 512, 0>,  cudaFuncAttributeMaxDynamicSharedMemorySize, SM_BYTES);
    cudaFuncSetAttribute(gemm_mma<512, 512, 2>,   cudaFuncAttributeMaxDynamicSharedMemorySize, SM_BYTES);
    cudaFuncSetAttribute(gemm_mma<2048, 512, 1>,  cudaFuncAttributeMaxDynamicSharedMemorySize, SM_BYTES);
    cudaFuncSetAttribute(gemm_mma<512, 2048, 3>,  cudaFuncAttributeMaxDynamicSharedMemorySize, SM_BYTES);

    f2h_all<<<512, 256>>>(qkvw, projw, f1w, f2w, wq, wp, w1, w2);
    build_tbl<<<(4 * 16 * 49 * 64 + 255) / 256, 256>>>(rpb, tbl);
    ln1_kernel<<<HW / 32, 256>>>(x, n1w, n1b, xw);
    gemm_mma<1536, 512, 0><<<dim3(1536 / BN, NTOK / BM), 256, SM_BYTES>>>(xw, wq, qkvb, nullptr, qkv);
    attn_kernel<<<256 * 16, 128>>>(qkv, tbl, att);
    gemm_mma<512, 512, 2><<<dim3(512 / BN, NTOK / BM), 256, SM_BYTES>>>(att, wp, projb, x, x1);
    ln2_kernel<<<HW, 256>>>(x1, n2w, n2b, x2);
    gemm_mma<2048, 512, 1><<<dim3(2048 / BN, NTOK / BM), 256, SM_BYTES>>>(x2, w1, f1b, nullptr, h);
    gemm_mma<512, 2048, 3><<<dim3(512 / BN, NTOK / BM), 256, SM_BYTES>>>(h, w2, f2b, x1, out);
}